// round 14
// baseline (speedup 1.0000x reference)
#include <cuda_runtime.h>
#include <cuda_bf16.h>
#include <cstdint>

// B=64, S=1024, D=64, U=128, NB=8, SIG_DIM=4160; final-KAN K = 64+512 = 576
// k_main: K = 36 ksteps of 16; N = 128 = 16 n-frags of 8.
// k_lin1: GRKAN layer-1 GEMMs, K order = [4160 silu | 33280 spline], plus skip.

__device__ float d_sig[64 * 4160];
__device__ float d_h1[64 * 128];
__device__ float d_h2g[64 * 128];
__device__ float d_skip[64 * 128];
__device__ float d_wts[64 * 128];
// B operand in m16n8k16 fragment layout: [kstep 36][nfrag 16][lane 32] = {bh0,bh1,bl0,bl1}
__device__ uint4 d_Bfrag[36 * 16 * 32];

__device__ __forceinline__ float siluf(float v) { return v / (1.f + __expf(-v)); }
__device__ __forceinline__ float sigmf(float v) { return 1.f / (1.f + __expf(-v)); }

// Cox-de Boor, GRID_SIZE=5, order 3, uniform knots g(k)=0.4k-2.2 -> 8 bases
__device__ __forceinline__ void bspline8(float x, float* o) {
    float bb[11];
#pragma unroll
    for (int k = 0; k < 11; k++) {
        float gk = 0.4f * k - 2.2f, gk1 = 0.4f * (k + 1) - 2.2f;
        bb[k] = (x >= gk && x < gk1) ? 1.f : 0.f;
    }
#pragma unroll
    for (int p = 1; p <= 3; p++) {
        float inv = 1.f / (0.4f * p);
#pragma unroll
        for (int k = 0; k + p < 11; k++) {
            float gk = 0.4f * k - 2.2f, gkp1 = 0.4f * (k + p + 1) - 2.2f;
            bb[k] = (x - gk) * inv * bb[k] + (gkp1 - x) * inv * bb[k + 1];
        }
    }
#pragma unroll
    for (int k = 0; k < 8; k++) o[k] = bb[k];
}

__device__ __forceinline__ void ffma2(unsigned long long& d, unsigned long long a,
                                      unsigned long long b) {
    asm("fma.rn.f32x2 %0, %1, %2, %0;" : "+l"(d) : "l"(a), "l"(b));
}
__device__ __forceinline__ unsigned long long bcast2(float v) {
    unsigned long long r; unsigned int u = __float_as_uint(v);
    asm("mov.b64 %0, {%1, %1};" : "=l"(r) : "r"(u));
    return r;
}
__device__ __forceinline__ float2 unpack2(unsigned long long v) {
    unsigned int lo, hi;
    asm("mov.b64 {%0, %1}, %2;" : "=r"(lo), "=r"(hi) : "l"(v));
    return make_float2(__uint_as_float(lo), __uint_as_float(hi));
}
// split fp32 pair -> packed bf16 hi pair + bf16 lo (residual) pair
__device__ __forceinline__ void split2(float a, float b, uint32_t& h, uint32_t& l) {
    __nv_bfloat16 ah = __float2bfloat16(a), bh = __float2bfloat16(b);
    __nv_bfloat16 al = __float2bfloat16(a - __bfloat162float(ah));
    __nv_bfloat16 bl = __float2bfloat16(b - __bfloat162float(bh));
    h = (uint32_t)__bfloat16_as_ushort(ah) | ((uint32_t)__bfloat16_as_ushort(bh) << 16);
    l = (uint32_t)__bfloat16_as_ushort(al) | ((uint32_t)__bfloat16_as_ushort(bl) << 16);
}
// m16n8k16 row.col bf16 MMA, fp32 accumulate in place
__device__ __forceinline__ void mma16816(float* d, uint32_t a0, uint32_t a1, uint32_t a2,
                                         uint32_t a3, uint32_t b0, uint32_t b1) {
    asm("mma.sync.aligned.m16n8k16.row.col.f32.bf16.bf16.f32 "
        "{%0,%1,%2,%3}, {%4,%5,%6,%7}, {%8,%9}, {%0,%1,%2,%3};"
        : "+f"(d[0]), "+f"(d[1]), "+f"(d[2]), "+f"(d[3])
        : "r"(a0), "r"(a1), "r"(a2), "r"(a3), "r"(b0), "r"(b1));
}

// ============ K0: init ============
__global__ void k_init(const float* __restrict__ x, const float* __restrict__ tw) {
    int idx = blockIdx.x * blockDim.x + threadIdx.x;
    if (idx < 64 * 4160) {
        int b = idx / 4160, r = idx - b * 4160;
        if (r < 64) {
            float wl = tw[1023] * x[((size_t)b * 1024 + 1023) * 64 + r];
            float w0 = tw[0]    * x[(size_t)b * 1024 * 64 + r];
            d_sig[idx] = wl - w0;
        } else d_sig[idx] = 0.f;
    }
    if (idx < 64 * 128) { d_h1[idx] = 0.f; d_skip[idx] = 0.f; d_h2g[idx] = 0.f; }
}

// ============ K-prep: kan W^T (576x128) -> bf16 hi/lo m16n8k16 B-fragment layout ==
__global__ void k_prep(const float* __restrict__ kan_base,
                       const float* __restrict__ kan_spline) {
    int idx = blockIdx.x * blockDim.x + threadIdx.x;
    if (idx >= 36 * 16 * 32) return;
    int l = idx & 31, f = (idx >> 5) & 15, s = idx >> 9;
    int n = f * 8 + (l >> 2);
    int k0 = s * 16 + (l & 3) * 2;
    float w[4];
#pragma unroll
    for (int q = 0; q < 4; q++) {
        int k = k0 + (q >> 1) * 8 + (q & 1);
        w[q] = (k < 64) ? kan_base[k * 128 + n] : kan_spline[(size_t)(k - 64) * 128 + n];
    }
    uint4 v;
    split2(w[0], w[1], v.x, v.z);
    split2(w[2], w[3], v.y, v.w);
    d_Bfrag[idx] = v;
}

// ============ K1: level-2 signature (unchanged) ============
#define KSIG_SMEM (2 * 128 * 64 * 4)
__global__ __launch_bounds__(256) void k_sig(const float* __restrict__ x,
                                             const float* __restrict__ tw) {
    extern __shared__ float sm[];
    float* sM = sm; float* sU = sm + 128 * 64;
    const int b = blockIdx.x, chunk = blockIdx.y, t0 = chunk * 128;
    const int steps = (chunk == 7) ? 127 : 128;
    const int tid = threadIdx.x;
    const size_t xb = (size_t)b * 1024 * 64;
    for (int e = tid; e < steps * 64; e += 256) {
        int t = e >> 6, d = e & 63;
        float wt0 = tw[t0 + t]     * x[xb + (size_t)(t0 + t) * 64 + d];
        float wt1 = tw[t0 + t + 1] * x[xb + (size_t)(t0 + t + 1) * 64 + d];
        float w0v = tw[0] * x[xb + d];
        sU[t * 64 + d] = wt1 - wt0;
        sM[t * 64 + d] = 0.5f * (wt0 + wt1) - w0v;
    }
    __syncthreads();
    const int jp = tid & 31, i0 = (tid >> 5) * 8;
    unsigned long long acc[8];
#pragma unroll
    for (int q = 0; q < 8; q++) acc[q] = 0ull;
#pragma unroll 2
    for (int t = 0; t < steps; t++) {
        const float4 m0 = *reinterpret_cast<const float4*>(&sM[t * 64 + i0]);
        const float4 m1 = *reinterpret_cast<const float4*>(&sM[t * 64 + i0 + 4]);
        const unsigned long long u2 =
            *reinterpret_cast<const unsigned long long*>(&sU[t * 64 + 2 * jp]);
        ffma2(acc[0], u2, bcast2(m0.x)); ffma2(acc[1], u2, bcast2(m0.y));
        ffma2(acc[2], u2, bcast2(m0.z)); ffma2(acc[3], u2, bcast2(m0.w));
        ffma2(acc[4], u2, bcast2(m1.x)); ffma2(acc[5], u2, bcast2(m1.y));
        ffma2(acc[6], u2, bcast2(m1.z)); ffma2(acc[7], u2, bcast2(m1.w));
    }
#pragma unroll
    for (int q = 0; q < 8; q++) {
        float2 f = unpack2(acc[q]);
        int i = i0 + q;
        atomicAdd(&d_sig[b * 4160 + 64 + i * 64 + 2 * jp],     f.x);
        atomicAdd(&d_sig[b * 4160 + 64 + i * 64 + 2 * jp + 1], f.y);
    }
}

// ============ K2: GRKAN layer 1 + skip via mma.sync ============
// K order: [silu(sig) 4160 | spline bases 33280] -> two pure GEMMs vs g1_base /
// g1_spline; plus skip = sig @ skip_w. 299 CTAs: [0,26) base, [26,234) spline
// (10 ksteps each), [234,299) skip (4 ksteps). B loaded directly from weights
// (4 sector-perfect LDG.32/frag), split to bf16 hi/lo on the fly. M=64 (4 mtiles),
// N=128 (warp = mtile x n-half). fp32 atomic accumulation into d_h1 / d_skip.
#define L1_SMEM (64 * 168 * 4)
__global__ __launch_bounds__(256) void k_lin1(const float* __restrict__ g1_base,
                                              const float* __restrict__ g1_spline,
                                              const float* __restrict__ skip_w) {
    extern __shared__ float feat[];            // [64][168] (pad 8)
    const int cid = blockIdx.x;
    const float* Bw;
    float* outp;
    int ks0, nks, mode;
    if (cid < 26)       { mode = 0; Bw = g1_base;   outp = d_h1;   ks0 = cid * 10;        nks = 10; }
    else if (cid < 234) { mode = 1; Bw = g1_spline; outp = d_h1;   ks0 = (cid - 26) * 10; nks = 10; }
    else                { mode = 2; Bw = skip_w;    outp = d_skip; ks0 = (cid - 234) * 4; nks = 4;  }
    const int tid = threadIdx.x;
    const int kk0 = ks0 * 16;
    // ---- stage A features: feat[b][i] for i in [0, nks*16) ----
    if (mode == 0) {
        for (int e = tid; e < 64 * 160; e += 256) {
            int b = e / 160, i = e - b * 160;
            feat[b * 168 + i] = siluf(d_sig[b * 4160 + kk0 + i]);
        }
    } else if (mode == 2) {
        for (int e = tid; e < 64 * 64; e += 256) {
            int b = e >> 6, i = e & 63;
            feat[b * 168 + i] = d_sig[b * 4160 + kk0 + i];
        }
    } else {
        const int d0 = kk0 >> 3;               // kk0 divisible by 8
        for (int e = tid; e < 64 * 20; e += 256) {
            int b = e / 20, dd = e - b * 20;
            float bas[8];
            bspline8(d_sig[b * 4160 + d0 + dd], bas);
#pragma unroll
            for (int nb = 0; nb < 8; nb++) feat[b * 168 + dd * 8 + nb] = bas[nb];
        }
    }
    __syncthreads();
    const int w = tid >> 5, lane = tid & 31;
    const int mt = w & 3, nh = w >> 2;
    const int wr = lane >> 2, kq = (lane & 3) * 2;
    const int m0 = mt * 16 + wr;               // rows m0, m0+8
    const int nbase = nh * 64;
    float acc[8][4];
#pragma unroll
    for (int f = 0; f < 8; f++)
#pragma unroll
        for (int q = 0; q < 4; q++) acc[f][q] = 0.f;

    for (int ks = 0; ks < nks; ks++) {
        const int kb = ks * 16 + kq;
        float2 f0 = *(const float2*)(&feat[m0 * 168 + kb]);
        float2 f1 = *(const float2*)(&feat[(m0 + 8) * 168 + kb]);
        float2 f2 = *(const float2*)(&feat[m0 * 168 + kb + 8]);
        float2 f3 = *(const float2*)(&feat[(m0 + 8) * 168 + kb + 8]);
        uint32_t ah[4], al[4];
        split2(f0.x, f0.y, ah[0], al[0]);
        split2(f1.x, f1.y, ah[1], al[1]);
        split2(f2.x, f2.y, ah[2], al[2]);
        split2(f3.x, f3.y, ah[3], al[3]);
        const float* Bp = Bw + (size_t)(kk0 + ks * 16 + kq) * 128;
#pragma unroll
        for (int f = 0; f < 8; f++) {
            const float* bp = Bp + nbase + f * 8 + wr;
            float w0 = bp[0];          // row kq
            float w1 = bp[128];        // row kq+1
            float w2 = bp[8 * 128];    // row kq+8
            float w3 = bp[9 * 128];    // row kq+9
            uint32_t bh0, bl0, bh1, bl1;
            split2(w0, w1, bh0, bl0);
            split2(w2, w3, bh1, bl1);
            mma16816(acc[f], ah[0], ah[1], ah[2], ah[3], bh0, bh1);  // hh
            mma16816(acc[f], ah[0], ah[1], ah[2], ah[3], bl0, bl1);  // hl
            mma16816(acc[f], al[0], al[1], al[2], al[3], bh0, bh1);  // lh
        }
    }
#pragma unroll
    for (int f = 0; f < 8; f++) {
        int c = nbase + f * 8 + (lane & 3) * 2;
        atomicAdd(&outp[m0 * 128 + c],           acc[f][0]);
        atomicAdd(&outp[m0 * 128 + c + 1],       acc[f][1]);
        atomicAdd(&outp[(m0 + 8) * 128 + c],     acc[f][2]);
        atomicAdd(&outp[(m0 + 8) * 128 + c + 1], acc[f][3]);
    }
}

// ============ K3a: h2 = kan_linear(h1, g2), split-K x4, 256 blocks ============
__global__ __launch_bounds__(128) void k_grkan2a(const float* __restrict__ g2_base,
                                                 const float* __restrict__ g2_spline) {
    __shared__ float s_sil[32];
    __shared__ float s_bas[32][8];
    const int b = blockIdx.x >> 2, kq = blockIdx.x & 3;
    const int u = threadIdx.x;
    const int k0 = kq * 32;
    if (u < 32) {
        float v = d_h1[b * 128 + k0 + u];
        s_sil[u] = siluf(v);
        bspline8(v, &s_bas[u][0]);
    }
    __syncthreads();
    float acc = 0.f;
#pragma unroll 8
    for (int kk = 0; kk < 32; kk++) {
        int k = k0 + kk;
        float h = s_sil[kk] * g2_base[k * 128 + u];
#pragma unroll
        for (int nb = 0; nb < 8; nb++)
            h += s_bas[kk][nb] * g2_spline[((size_t)k * 8 + nb) * 128 + u];
        acc += h;
    }
    atomicAdd(&d_h2g[b * 128 + u], acc);
}

// ============ K3b: gate + layernorm + softmax -> d_wts (64 blocks x 128) ============
__device__ __forceinline__ float bsum128(float v, volatile float* red) {
#pragma unroll
    for (int o = 16; o > 0; o >>= 1) v += __shfl_xor_sync(0xffffffffu, v, o);
    int w = threadIdx.x >> 5;
    __syncthreads();
    if ((threadIdx.x & 31) == 0) red[w] = v;
    __syncthreads();
    return red[0] + red[1] + red[2] + red[3];
}
__device__ __forceinline__ float bmax128(float v, volatile float* red) {
#pragma unroll
    for (int o = 16; o > 0; o >>= 1) v = fmaxf(v, __shfl_xor_sync(0xffffffffu, v, o));
    int w = threadIdx.x >> 5;
    __syncthreads();
    if ((threadIdx.x & 31) == 0) red[w] = v;
    __syncthreads();
    return fmaxf(fmaxf(red[0], red[1]), fmaxf(red[2], red[3]));
}
__global__ __launch_bounds__(128) void k_grkan2b(
    const float* __restrict__ skip_b,
    const float* __restrict__ gate_ws, const float* __restrict__ gate_bs,
    const float* __restrict__ gate_wv, const float* __restrict__ gate_bv,
    const float* __restrict__ ln_g, const float* __restrict__ ln_b) {
    __shared__ float s_h2[128];
    __shared__ float red[4];
    const int b = blockIdx.x;
    const int u = threadIdx.x;
    s_h2[u] = d_h2g[b * 128 + u];
    __syncthreads();
    float sa = 0.f, va = 0.f;
#pragma unroll 8
    for (int k = 0; k < 128; k++) {
        float h = s_h2[k];
        sa += h * gate_ws[k * 128 + u];
        va += h * gate_wv[k * 128 + u];
    }
    float gate = sigmf(sa + gate_bs[u]) * (va + gate_bv[u]);
    float y = d_skip[b * 128 + u] + skip_b[u] + gate;
    float mu = bsum128(y, red) * (1.f / 128.f);
    float dv = y - mu;
    float var = bsum128(dv * dv, red) * (1.f / 128.f);
    float z = ln_g[u] * dv / sqrtf(var + 1e-3f) + ln_b[u];
    float mx = bmax128(z, red);
    float ez = __expf(z - mx);
    float es = bsum128(ez, red);
    d_wts[b * 128 + u] = ez / es;
}

// ============ K4: final KAN via mma.sync bf16 split precision (unchanged) ============
#define KM_SMEM    (8192 * 4 + 64 * 129 * 4 + 512)
__global__ __launch_bounds__(256, 1) void k_main(const float* __restrict__ x,
                                                 const float* __restrict__ tw,
                                                 float* __restrict__ out) {
    extern __shared__ float smf[];
    uint32_t* Ah = (uint32_t*)smf;                    // [4 sl][8 rt][32 lane][4 regs]
    uint32_t* Al = Ah + 4096;
    float* xt    = smf + 8192;                        // x^T tile [64][129]
    float* wts_s = xt + 64 * 129;
    const int tid = threadIdx.x, w = tid >> 5, lane = tid & 31;
    const int tile = blockIdx.x;
    const size_t row0 = (size_t)tile * 128;

    for (int e = tid; e < 2048; e += 256) {
        float4 v = ((const float4*)(x + row0 * 64))[e];
        int r = e >> 4, dd = (e & 15) * 4;
        xt[(dd + 0) * 129 + r] = v.x;
        xt[(dd + 1) * 129 + r] = v.y;
        xt[(dd + 2) * 129 + r] = v.z;
        xt[(dd + 3) * 129 + r] = v.w;
    }
    if (tid < 128) wts_s[tid] = d_wts[(tile >> 3) * 128 + tid];

    float acc[16][4];
#pragma unroll
    for (int f = 0; f < 16; f++)
#pragma unroll
        for (int q = 0; q < 4; q++) acc[f][q] = 0.f;

    for (int c = 0; c < 9; c++) {
        __syncthreads();
#pragma unroll
        for (int j = 0; j < 4; j++) {
            int it = tid + j * 256;          // 1024 items: [dl 8][r 128]
            int r = it & 127, dl = it >> 7;
            int rt = r >> 4, wr = r & 15, gid = wr & 7;
            int reg = ((wr < 8) ? 0 : 1) + (dl & 1) * 2;
            int slot = (((dl >> 1) * 8 + rt) * 32 + gid * 4) * 4 + reg;
            float t = tw[(row0 + r) & 1023];
            float vals[8];
            if (c == 0) {
#pragma unroll
                for (int nb = 0; nb < 8; nb++)
                    vals[nb] = siluf(t * xt[(dl * 8 + nb) * 129 + r]);
            } else {
                float wv = t * xt[(8 * (c - 1) + dl) * 129 + r];
                bspline8(wv, vals);
            }
#pragma unroll
            for (int pj = 0; pj < 4; pj++) {
                uint32_t h, l;
                split2(vals[2 * pj], vals[2 * pj + 1], h, l);
                Ah[slot + pj * 4] = h;
                Al[slot + pj * 4] = l;
            }
        }
        __syncthreads();
#pragma unroll
        for (int sl = 0; sl < 4; sl++) {
            const uint4 a_h = ((const uint4*)Ah)[(sl * 8 + w) * 32 + lane];
            const uint4 a_l = ((const uint4*)Al)[(sl * 8 + w) * 32 + lane];
            const uint4* Bp = d_Bfrag + ((c * 4 + sl) * 16) * 32 + lane;
#pragma unroll
            for (int f = 0; f < 16; f++) {
                const uint4 b = Bp[f * 32];
                mma16816(acc[f], a_h.x, a_h.y, a_h.z, a_h.w, b.x, b.y);  // hh
                mma16816(acc[f], a_h.x, a_h.y, a_h.z, a_h.w, b.z, b.w);  // hl
                mma16816(acc[f], a_l.x, a_l.y, a_l.z, a_l.w, b.x, b.y);  // lh
            }
        }
    }
    __syncthreads();

    const int rlo = w * 16 + (lane >> 2);
#pragma unroll
    for (int f = 0; f < 16; f++) {
        int c0 = f * 8 + (lane & 3) * 2;
        float w0 = wts_s[c0], w1 = wts_s[c0 + 1];
        float2 v0 = make_float2(acc[f][0] * w0, acc[f][1] * w1);
        float2 v1 = make_float2(acc[f][2] * w0, acc[f][3] * w1);
        *(float2*)(out + (row0 + rlo) * 128 + c0)     = v0;
        *(float2*)(out + (row0 + rlo + 8) * 128 + c0) = v1;
    }
}

extern "C" void kernel_launch(void* const* d_in, const int* in_sizes, int n_in,
                              void* d_out, int out_size) {
    const float* x          = (const float*)d_in[0];
    const float* tw         = (const float*)d_in[1];
    const float* kan_base   = (const float*)d_in[2];
    const float* kan_spline = (const float*)d_in[3];
    const float* g1_base    = (const float*)d_in[4];
    const float* g1_spline  = (const float*)d_in[5];
    const float* g2_base    = (const float*)d_in[6];
    const float* g2_spline  = (const float*)d_in[7];
    const float* skip_w     = (const float*)d_in[8];
    const float* skip_b     = (const float*)d_in[9];
    const float* gate_ws    = (const float*)d_in[10];
    const float* gate_bs    = (const float*)d_in[11];
    const float* gate_wv    = (const float*)d_in[12];
    const float* gate_bv    = (const float*)d_in[13];
    const float* ln_g       = (const float*)d_in[14];
    const float* ln_b       = (const float*)d_in[15];
    float* out = (float*)d_out;

    cudaFuncSetAttribute(k_sig,  cudaFuncAttributeMaxDynamicSharedMemorySize, KSIG_SMEM);
    cudaFuncSetAttribute(k_main, cudaFuncAttributeMaxDynamicSharedMemorySize, KM_SMEM);

    k_init<<<(64 * 4160 + 255) / 256, 256>>>(x, tw);
    k_prep<<<72, 256>>>(kan_base, kan_spline);
    k_sig<<<dim3(64, 8), 256, KSIG_SMEM>>>(x, tw);
    k_lin1<<<299, 256, L1_SMEM>>>(g1_base, g1_spline, skip_w);
    k_grkan2a<<<256, 128>>>(g2_base, g2_spline);
    k_grkan2b<<<64, 128>>>(skip_b, gate_ws, gate_bs, gate_wv, gate_bv, ln_g, ln_b);
    k_main<<<512, 256, KM_SMEM>>>(x, tw, out);
}

// round 15
// speedup vs baseline: 1.4187x; 1.4187x over previous
#include <cuda_runtime.h>
#include <cuda_bf16.h>
#include <cstdint>

// B=64, S=1024, D=64, U=128, NB=8, SIG_DIM=4160; final-KAN K = 64+512 = 576
// k_main: K = 36 ksteps of 16; N = 128 = 16 n-frags of 8.
// k_lin1: GRKAN layer-1 GEMMs, K order = [4160 silu | 33280 spline], plus skip.

__device__ float d_sig[64 * 4160];
__device__ float d_h1[64 * 128];
__device__ float d_h2g[64 * 128];
__device__ float d_skip[64 * 128];
__device__ float d_wts[64 * 128];
// B operand in m16n8k16 fragment layout: [kstep 36][nfrag 16][lane 32] = {bh0,bh1,bl0,bl1}
__device__ uint4 d_Bfrag[36 * 16 * 32];

__device__ __forceinline__ float siluf(float v) { return v / (1.f + __expf(-v)); }
__device__ __forceinline__ float sigmf(float v) { return 1.f / (1.f + __expf(-v)); }

// Cox-de Boor, GRID_SIZE=5, order 3, uniform knots g(k)=0.4k-2.2 -> 8 bases
__device__ __forceinline__ void bspline8(float x, float* o) {
    float bb[11];
#pragma unroll
    for (int k = 0; k < 11; k++) {
        float gk = 0.4f * k - 2.2f, gk1 = 0.4f * (k + 1) - 2.2f;
        bb[k] = (x >= gk && x < gk1) ? 1.f : 0.f;
    }
#pragma unroll
    for (int p = 1; p <= 3; p++) {
        float inv = 1.f / (0.4f * p);
#pragma unroll
        for (int k = 0; k + p < 11; k++) {
            float gk = 0.4f * k - 2.2f, gkp1 = 0.4f * (k + p + 1) - 2.2f;
            bb[k] = (x - gk) * inv * bb[k] + (gkp1 - x) * inv * bb[k + 1];
        }
    }
#pragma unroll
    for (int k = 0; k < 8; k++) o[k] = bb[k];
}

__device__ __forceinline__ void ffma2(unsigned long long& d, unsigned long long a,
                                      unsigned long long b) {
    asm("fma.rn.f32x2 %0, %1, %2, %0;" : "+l"(d) : "l"(a), "l"(b));
}
__device__ __forceinline__ unsigned long long bcast2(float v) {
    unsigned long long r; unsigned int u = __float_as_uint(v);
    asm("mov.b64 %0, {%1, %1};" : "=l"(r) : "r"(u));
    return r;
}
__device__ __forceinline__ float2 unpack2(unsigned long long v) {
    unsigned int lo, hi;
    asm("mov.b64 {%0, %1}, %2;" : "=r"(lo), "=r"(hi) : "l"(v));
    return make_float2(__uint_as_float(lo), __uint_as_float(hi));
}
// split fp32 pair -> packed bf16 hi pair + bf16 lo (residual) pair
__device__ __forceinline__ void split2(float a, float b, uint32_t& h, uint32_t& l) {
    __nv_bfloat16 ah = __float2bfloat16(a), bh = __float2bfloat16(b);
    __nv_bfloat16 al = __float2bfloat16(a - __bfloat162float(ah));
    __nv_bfloat16 bl = __float2bfloat16(b - __bfloat162float(bh));
    h = (uint32_t)__bfloat16_as_ushort(ah) | ((uint32_t)__bfloat16_as_ushort(bh) << 16);
    l = (uint32_t)__bfloat16_as_ushort(al) | ((uint32_t)__bfloat16_as_ushort(bl) << 16);
}
// m16n8k16 row.col bf16 MMA, fp32 accumulate in place
__device__ __forceinline__ void mma16816(float* d, uint32_t a0, uint32_t a1, uint32_t a2,
                                         uint32_t a3, uint32_t b0, uint32_t b1) {
    asm("mma.sync.aligned.m16n8k16.row.col.f32.bf16.bf16.f32 "
        "{%0,%1,%2,%3}, {%4,%5,%6,%7}, {%8,%9}, {%0,%1,%2,%3};"
        : "+f"(d[0]), "+f"(d[1]), "+f"(d[2]), "+f"(d[3])
        : "r"(a0), "r"(a1), "r"(a2), "r"(a3), "r"(b0), "r"(b1));
}

// ============ K0: init ============
__global__ void k_init(const float* __restrict__ x, const float* __restrict__ tw) {
    int idx = blockIdx.x * blockDim.x + threadIdx.x;
    if (idx < 64 * 4160) {
        int b = idx / 4160, r = idx - b * 4160;
        if (r < 64) {
            float wl = tw[1023] * x[((size_t)b * 1024 + 1023) * 64 + r];
            float w0 = tw[0]    * x[(size_t)b * 1024 * 64 + r];
            d_sig[idx] = wl - w0;
        } else d_sig[idx] = 0.f;
    }
    if (idx < 64 * 128) { d_h1[idx] = 0.f; d_skip[idx] = 0.f; d_h2g[idx] = 0.f; }
}

// ============ K-prep: kan W^T (576x128) -> bf16 hi/lo m16n8k16 B-fragment layout ==
__global__ void k_prep(const float* __restrict__ kan_base,
                       const float* __restrict__ kan_spline) {
    int idx = blockIdx.x * blockDim.x + threadIdx.x;
    if (idx >= 36 * 16 * 32) return;
    int l = idx & 31, f = (idx >> 5) & 15, s = idx >> 9;
    int n = f * 8 + (l >> 2);
    int k0 = s * 16 + (l & 3) * 2;
    float w[4];
#pragma unroll
    for (int q = 0; q < 4; q++) {
        int k = k0 + (q >> 1) * 8 + (q & 1);
        w[q] = (k < 64) ? kan_base[k * 128 + n] : kan_spline[(size_t)(k - 64) * 128 + n];
    }
    uint4 v;
    split2(w[0], w[1], v.x, v.z);
    split2(w[2], w[3], v.y, v.w);
    d_Bfrag[idx] = v;
}

// ============ K1: level-2 signature (unchanged) ============
#define KSIG_SMEM (2 * 128 * 64 * 4)
__global__ __launch_bounds__(256) void k_sig(const float* __restrict__ x,
                                             const float* __restrict__ tw) {
    extern __shared__ float sm[];
    float* sM = sm; float* sU = sm + 128 * 64;
    const int b = blockIdx.x, chunk = blockIdx.y, t0 = chunk * 128;
    const int steps = (chunk == 7) ? 127 : 128;
    const int tid = threadIdx.x;
    const size_t xb = (size_t)b * 1024 * 64;
    for (int e = tid; e < steps * 64; e += 256) {
        int t = e >> 6, d = e & 63;
        float wt0 = tw[t0 + t]     * x[xb + (size_t)(t0 + t) * 64 + d];
        float wt1 = tw[t0 + t + 1] * x[xb + (size_t)(t0 + t + 1) * 64 + d];
        float w0v = tw[0] * x[xb + d];
        sU[t * 64 + d] = wt1 - wt0;
        sM[t * 64 + d] = 0.5f * (wt0 + wt1) - w0v;
    }
    __syncthreads();
    const int jp = tid & 31, i0 = (tid >> 5) * 8;
    unsigned long long acc[8];
#pragma unroll
    for (int q = 0; q < 8; q++) acc[q] = 0ull;
#pragma unroll 2
    for (int t = 0; t < steps; t++) {
        const float4 m0 = *reinterpret_cast<const float4*>(&sM[t * 64 + i0]);
        const float4 m1 = *reinterpret_cast<const float4*>(&sM[t * 64 + i0 + 4]);
        const unsigned long long u2 =
            *reinterpret_cast<const unsigned long long*>(&sU[t * 64 + 2 * jp]);
        ffma2(acc[0], u2, bcast2(m0.x)); ffma2(acc[1], u2, bcast2(m0.y));
        ffma2(acc[2], u2, bcast2(m0.z)); ffma2(acc[3], u2, bcast2(m0.w));
        ffma2(acc[4], u2, bcast2(m1.x)); ffma2(acc[5], u2, bcast2(m1.y));
        ffma2(acc[6], u2, bcast2(m1.z)); ffma2(acc[7], u2, bcast2(m1.w));
    }
#pragma unroll
    for (int q = 0; q < 8; q++) {
        float2 f = unpack2(acc[q]);
        int i = i0 + q;
        atomicAdd(&d_sig[b * 4160 + 64 + i * 64 + 2 * jp],     f.x);
        atomicAdd(&d_sig[b * 4160 + 64 + i * 64 + 2 * jp + 1], f.y);
    }
}

// ============ K2: GRKAN layer 1 + skip via mma.sync — split-K x2 finer ============
// 533 CTAs: [0,52) base (5 ksteps), [52,468) spline (5 ksteps), [468,533) skip (4).
// smem stride 88 (22.5KB) for higher residency. fp32 atomics into d_h1 / d_skip.
#define L1_SMEM (64 * 88 * 4)
__global__ __launch_bounds__(256) void k_lin1(const float* __restrict__ g1_base,
                                              const float* __restrict__ g1_spline,
                                              const float* __restrict__ skip_w) {
    extern __shared__ float feat[];            // [64][88] (pad 8)
    const int cid = blockIdx.x;
    const float* Bw;
    float* outp;
    int ks0, nks, mode;
    if (cid < 52)       { mode = 0; Bw = g1_base;   outp = d_h1;   ks0 = cid * 5;         nks = 5; }
    else if (cid < 468) { mode = 1; Bw = g1_spline; outp = d_h1;   ks0 = (cid - 52) * 5;  nks = 5; }
    else                { mode = 2; Bw = skip_w;    outp = d_skip; ks0 = (cid - 468) * 4; nks = 4; }
    const int tid = threadIdx.x;
    const int kk0 = ks0 * 16;
    // ---- stage A features: feat[b][i] for i in [0, nks*16) ----
    if (mode == 0) {
        for (int e = tid; e < 64 * 80; e += 256) {
            int b = e / 80, i = e - b * 80;
            feat[b * 88 + i] = siluf(d_sig[b * 4160 + kk0 + i]);
        }
    } else if (mode == 2) {
        for (int e = tid; e < 64 * 64; e += 256) {
            int b = e >> 6, i = e & 63;
            feat[b * 88 + i] = d_sig[b * 4160 + kk0 + i];
        }
    } else {
        const int d0 = kk0 >> 3;               // kk0 divisible by 8
        for (int e = tid; e < 64 * 10; e += 256) {
            int b = e / 10, dd = e - b * 10;
            float bas[8];
            bspline8(d_sig[b * 4160 + d0 + dd], bas);
#pragma unroll
            for (int nb = 0; nb < 8; nb++) feat[b * 88 + dd * 8 + nb] = bas[nb];
        }
    }
    __syncthreads();
    const int w = tid >> 5, lane = tid & 31;
    const int mt = w & 3, nh = w >> 2;
    const int wr = lane >> 2, kq = (lane & 3) * 2;
    const int m0 = mt * 16 + wr;               // rows m0, m0+8
    const int nbase = nh * 64;
    float acc[8][4];
#pragma unroll
    for (int f = 0; f < 8; f++)
#pragma unroll
        for (int q = 0; q < 4; q++) acc[f][q] = 0.f;

    for (int ks = 0; ks < nks; ks++) {
        const int kb = ks * 16 + kq;
        float2 f0 = *(const float2*)(&feat[m0 * 88 + kb]);
        float2 f1 = *(const float2*)(&feat[(m0 + 8) * 88 + kb]);
        float2 f2 = *(const float2*)(&feat[m0 * 88 + kb + 8]);
        float2 f3 = *(const float2*)(&feat[(m0 + 8) * 88 + kb + 8]);
        uint32_t ah[4], al[4];
        split2(f0.x, f0.y, ah[0], al[0]);
        split2(f1.x, f1.y, ah[1], al[1]);
        split2(f2.x, f2.y, ah[2], al[2]);
        split2(f3.x, f3.y, ah[3], al[3]);
        const float* Bp = Bw + (size_t)(kk0 + ks * 16 + kq) * 128;
#pragma unroll
        for (int f = 0; f < 8; f++) {
            const float* bp = Bp + nbase + f * 8 + wr;
            float w0 = bp[0];          // row kq
            float w1 = bp[128];        // row kq+1
            float w2 = bp[8 * 128];    // row kq+8
            float w3 = bp[9 * 128];    // row kq+9
            uint32_t bh0, bl0, bh1, bl1;
            split2(w0, w1, bh0, bl0);
            split2(w2, w3, bh1, bl1);
            mma16816(acc[f], ah[0], ah[1], ah[2], ah[3], bh0, bh1);  // hh
            mma16816(acc[f], ah[0], ah[1], ah[2], ah[3], bl0, bl1);  // hl
            mma16816(acc[f], al[0], al[1], al[2], al[3], bh0, bh1);  // lh
        }
    }
#pragma unroll
    for (int f = 0; f < 8; f++) {
        int c = nbase + f * 8 + (lane & 3) * 2;
        atomicAdd(&outp[m0 * 128 + c],           acc[f][0]);
        atomicAdd(&outp[m0 * 128 + c + 1],       acc[f][1]);
        atomicAdd(&outp[(m0 + 8) * 128 + c],     acc[f][2]);
        atomicAdd(&outp[(m0 + 8) * 128 + c + 1], acc[f][3]);
    }
}

// ============ K3a: h2 = kan_linear(h1, g2), split-K x4, 256 blocks ============
__global__ __launch_bounds__(128) void k_grkan2a(const float* __restrict__ g2_base,
                                                 const float* __restrict__ g2_spline) {
    __shared__ float s_sil[32];
    __shared__ float s_bas[32][8];
    const int b = blockIdx.x >> 2, kq = blockIdx.x & 3;
    const int u = threadIdx.x;
    const int k0 = kq * 32;
    if (u < 32) {
        float v = d_h1[b * 128 + k0 + u];
        s_sil[u] = siluf(v);
        bspline8(v, &s_bas[u][0]);
    }
    __syncthreads();
    float acc = 0.f;
#pragma unroll 8
    for (int kk = 0; kk < 32; kk++) {
        int k = k0 + kk;
        float h = s_sil[kk] * g2_base[k * 128 + u];
#pragma unroll
        for (int nb = 0; nb < 8; nb++)
            h += s_bas[kk][nb] * g2_spline[((size_t)k * 8 + nb) * 128 + u];
        acc += h;
    }
    atomicAdd(&d_h2g[b * 128 + u], acc);
}

// ============ K3b: gate + layernorm + softmax -> d_wts (64 blocks x 128) ============
__device__ __forceinline__ float bsum128(float v, volatile float* red) {
#pragma unroll
    for (int o = 16; o > 0; o >>= 1) v += __shfl_xor_sync(0xffffffffu, v, o);
    int w = threadIdx.x >> 5;
    __syncthreads();
    if ((threadIdx.x & 31) == 0) red[w] = v;
    __syncthreads();
    return red[0] + red[1] + red[2] + red[3];
}
__device__ __forceinline__ float bmax128(float v, volatile float* red) {
#pragma unroll
    for (int o = 16; o > 0; o >>= 1) v = fmaxf(v, __shfl_xor_sync(0xffffffffu, v, o));
    int w = threadIdx.x >> 5;
    __syncthreads();
    if ((threadIdx.x & 31) == 0) red[w] = v;
    __syncthreads();
    return fmaxf(fmaxf(red[0], red[1]), fmaxf(red[2], red[3]));
}
__global__ __launch_bounds__(128) void k_grkan2b(
    const float* __restrict__ skip_b,
    const float* __restrict__ gate_ws, const float* __restrict__ gate_bs,
    const float* __restrict__ gate_wv, const float* __restrict__ gate_bv,
    const float* __restrict__ ln_g, const float* __restrict__ ln_b) {
    __shared__ float s_h2[128];
    __shared__ float red[4];
    const int b = blockIdx.x;
    const int u = threadIdx.x;
    s_h2[u] = d_h2g[b * 128 + u];
    __syncthreads();
    float sa = 0.f, va = 0.f;
#pragma unroll 8
    for (int k = 0; k < 128; k++) {
        float h = s_h2[k];
        sa += h * gate_ws[k * 128 + u];
        va += h * gate_wv[k * 128 + u];
    }
    float gate = sigmf(sa + gate_bs[u]) * (va + gate_bv[u]);
    float y = d_skip[b * 128 + u] + skip_b[u] + gate;
    float mu = bsum128(y, red) * (1.f / 128.f);
    float dv = y - mu;
    float var = bsum128(dv * dv, red) * (1.f / 128.f);
    float z = ln_g[u] * dv / sqrtf(var + 1e-3f) + ln_b[u];
    float mx = bmax128(z, red);
    float ez = __expf(z - mx);
    float es = bsum128(ez, red);
    d_wts[b * 128 + u] = ez / es;
}

// ============ K4: final KAN via mma.sync bf16 split precision ============
// 256 CTAs x 2 tiles each (one uniform resident wave at ~2 CTAs/SM).
#define KM_SMEM    (8192 * 4 + 64 * 129 * 4 + 512)
__global__ __launch_bounds__(256, 1) void k_main(const float* __restrict__ x,
                                                 const float* __restrict__ tw,
                                                 float* __restrict__ out) {
    extern __shared__ float smf[];
    uint32_t* Ah = (uint32_t*)smf;                    // [4 sl][8 rt][32 lane][4 regs]
    uint32_t* Al = Ah + 4096;
    float* xt    = smf + 8192;                        // x^T tile [64][129]
    float* wts_s = xt + 64 * 129;
    const int tid = threadIdx.x, w = tid >> 5, lane = tid & 31;

    for (int tt = 0; tt < 2; tt++) {
        const int tile = blockIdx.x + tt * 256;
        const size_t row0 = (size_t)tile * 128;

        for (int e = tid; e < 2048; e += 256) {
            float4 v = ((const float4*)(x + row0 * 64))[e];
            int r = e >> 4, dd = (e & 15) * 4;
            xt[(dd + 0) * 129 + r] = v.x;
            xt[(dd + 1) * 129 + r] = v.y;
            xt[(dd + 2) * 129 + r] = v.z;
            xt[(dd + 3) * 129 + r] = v.w;
        }
        if (tid < 128) wts_s[tid] = d_wts[(tile >> 3) * 128 + tid];

        float acc[16][4];
#pragma unroll
        for (int f = 0; f < 16; f++)
#pragma unroll
            for (int q = 0; q < 4; q++) acc[f][q] = 0.f;

        for (int c = 0; c < 9; c++) {
            __syncthreads();        // staging/A-buffer visible & free
#pragma unroll
            for (int j = 0; j < 4; j++) {
                int it = tid + j * 256;          // 1024 items: [dl 8][r 128]
                int r = it & 127, dl = it >> 7;
                int rt = r >> 4, wr = r & 15, gid = wr & 7;
                int reg = ((wr < 8) ? 0 : 1) + (dl & 1) * 2;
                int slot = (((dl >> 1) * 8 + rt) * 32 + gid * 4) * 4 + reg;
                float t = tw[(row0 + r) & 1023];
                float vals[8];
                if (c == 0) {
#pragma unroll
                    for (int nb = 0; nb < 8; nb++)
                        vals[nb] = siluf(t * xt[(dl * 8 + nb) * 129 + r]);
                } else {
                    float wv = t * xt[(8 * (c - 1) + dl) * 129 + r];
                    bspline8(wv, vals);
                }
#pragma unroll
                for (int pj = 0; pj < 4; pj++) {
                    uint32_t h, l;
                    split2(vals[2 * pj], vals[2 * pj + 1], h, l);
                    Ah[slot + pj * 4] = h;
                    Al[slot + pj * 4] = l;
                }
            }
            __syncthreads();
#pragma unroll
            for (int sl = 0; sl < 4; sl++) {
                const uint4 a_h = ((const uint4*)Ah)[(sl * 8 + w) * 32 + lane];
                const uint4 a_l = ((const uint4*)Al)[(sl * 8 + w) * 32 + lane];
                const uint4* Bp = d_Bfrag + ((c * 4 + sl) * 16) * 32 + lane;
#pragma unroll
                for (int f = 0; f < 16; f++) {
                    const uint4 b = Bp[f * 32];
                    mma16816(acc[f], a_h.x, a_h.y, a_h.z, a_h.w, b.x, b.y);  // hh
                    mma16816(acc[f], a_h.x, a_h.y, a_h.z, a_h.w, b.z, b.w);  // hl
                    mma16816(acc[f], a_l.x, a_l.y, a_l.z, a_l.w, b.x, b.y);  // lh
                }
            }
        }
        __syncthreads();

        const int rlo = w * 16 + (lane >> 2);
#pragma unroll
        for (int f = 0; f < 16; f++) {
            int c0 = f * 8 + (lane & 3) * 2;
            float w0 = wts_s[c0], w1 = wts_s[c0 + 1];
            float2 v0 = make_float2(acc[f][0] * w0, acc[f][1] * w1);
            float2 v1 = make_float2(acc[f][2] * w0, acc[f][3] * w1);
            *(float2*)(out + (row0 + rlo) * 128 + c0)     = v0;
            *(float2*)(out + (row0 + rlo + 8) * 128 + c0) = v1;
        }
        __syncthreads();        // epilogue done before next tile overwrites buffers
    }
}

extern "C" void kernel_launch(void* const* d_in, const int* in_sizes, int n_in,
                              void* d_out, int out_size) {
    const float* x          = (const float*)d_in[0];
    const float* tw         = (const float*)d_in[1];
    const float* kan_base   = (const float*)d_in[2];
    const float* kan_spline = (const float*)d_in[3];
    const float* g1_base    = (const float*)d_in[4];
    const float* g1_spline  = (const float*)d_in[5];
    const float* g2_base    = (const float*)d_in[6];
    const float* g2_spline  = (const float*)d_in[7];
    const float* skip_w     = (const float*)d_in[8];
    const float* skip_b     = (const float*)d_in[9];
    const float* gate_ws    = (const float*)d_in[10];
    const float* gate_bs    = (const float*)d_in[11];
    const float* gate_wv    = (const float*)d_in[12];
    const float* gate_bv    = (const float*)d_in[13];
    const float* ln_g       = (const float*)d_in[14];
    const float* ln_b       = (const float*)d_in[15];
    float* out = (float*)d_out;

    cudaFuncSetAttribute(k_sig,  cudaFuncAttributeMaxDynamicSharedMemorySize, KSIG_SMEM);
    cudaFuncSetAttribute(k_main, cudaFuncAttributeMaxDynamicSharedMemorySize, KM_SMEM);

    k_init<<<(64 * 4160 + 255) / 256, 256>>>(x, tw);
    k_prep<<<72, 256>>>(kan_base, kan_spline);
    k_sig<<<dim3(64, 8), 256, KSIG_SMEM>>>(x, tw);
    k_lin1<<<533, 256, L1_SMEM>>>(g1_base, g1_spline, skip_w);
    k_grkan2a<<<256, 128>>>(g2_base, g2_spline);
    k_grkan2b<<<64, 128>>>(skip_b, gate_ws, gate_bs, gate_wv, gate_bv, ln_g, ln_b);
    k_main<<<256, 256, KM_SMEM>>>(x, tw, out);
}

// round 16
// speedup vs baseline: 1.7539x; 1.2363x over previous
#include <cuda_runtime.h>
#include <cuda_bf16.h>
#include <cstdint>

// B=64, S=1024, D=64, U=128, NB=8, SIG_DIM=4160; final-KAN K = 64+512 = 576
// k_main: K = 36 ksteps of 16; N = 128 = 16 n-frags of 8.
// k_lin1: GRKAN layer-1 GEMMs, K order = [4160 silu | 33280 spline], plus skip.

__device__ float d_sig[64 * 4160];
__device__ float d_h1[64 * 128];
__device__ float d_h2g[64 * 128];
__device__ float d_skip[64 * 128];
__device__ float d_wts[64 * 128];
// B operand in m16n8k16 fragment layout: [kstep 36][nfrag 16][lane 32] = {bh0,bh1,bl0,bl1}
__device__ uint4 d_Bfrag[36 * 16 * 32];

__device__ __forceinline__ float siluf(float v) { return v / (1.f + __expf(-v)); }
__device__ __forceinline__ float sigmf(float v) { return 1.f / (1.f + __expf(-v)); }

// Cubic B-spline on uniform knots g(k)=0.4k-2.2: only 4 consecutive bases are
// nonzero. Closed-form uniform segment polynomials + selects (CSE-able setp on i).
// Identical math to Cox-de Boor on this uniform grid.
__device__ __forceinline__ void bspline8(float x, float* o) {
    float xi = (x + 2.2f) * 2.5f;          // knot-space position
    float fi = floorf(xi);
    float t = xi - fi;
    int i = (int)fi;                        // interval; basis k nonzero iff i-3<=k<=i
    float t2 = t * t, t3 = t2 * t;
    float u = 1.f - t;
    float s0 = t3 * (1.f / 6.f);                            // segment 0 (k=i)
    float s1 = (1.f / 6.f) + 0.5f * t + 0.5f * t2 - 0.5f * t3;
    float s2 = (4.f / 6.f) - t2 + 0.5f * t3;
    float s3 = u * u * u * (1.f / 6.f);                     // segment 3 (k=i-3)
#pragma unroll
    for (int k = 0; k < 8; k++) {
        float v = (i == k) ? s0 : 0.f;
        v = (i == k + 1) ? s1 : v;
        v = (i == k + 2) ? s2 : v;
        v = (i == k + 3) ? s3 : v;
        o[k] = v;
    }
}

__device__ __forceinline__ void ffma2(unsigned long long& d, unsigned long long a,
                                      unsigned long long b) {
    asm("fma.rn.f32x2 %0, %1, %2, %0;" : "+l"(d) : "l"(a), "l"(b));
}
__device__ __forceinline__ unsigned long long bcast2(float v) {
    unsigned long long r; unsigned int u = __float_as_uint(v);
    asm("mov.b64 %0, {%1, %1};" : "=l"(r) : "r"(u));
    return r;
}
__device__ __forceinline__ float2 unpack2(unsigned long long v) {
    unsigned int lo, hi;
    asm("mov.b64 {%0, %1}, %2;" : "=r"(lo), "=r"(hi) : "l"(v));
    return make_float2(__uint_as_float(lo), __uint_as_float(hi));
}
// split fp32 pair -> packed bf16 hi pair + bf16 lo (residual) pair.
// Fast path: packed cvt + shift-based bf16->f32 (residual is exact in f32).
__device__ __forceinline__ void split2(float a, float b, uint32_t& h, uint32_t& l) {
    uint32_t hh;
    asm("cvt.rn.bf16x2.f32 %0, %1, %2;" : "=r"(hh) : "f"(b), "f"(a));  // lo=a, hi=b
    float ra = a - __uint_as_float(hh << 16);
    float rb = b - __uint_as_float(hh & 0xFFFF0000u);
    uint32_t ll;
    asm("cvt.rn.bf16x2.f32 %0, %1, %2;" : "=r"(ll) : "f"(rb), "f"(ra));
    h = hh; l = ll;
}
// m16n8k16 row.col bf16 MMA, fp32 accumulate in place
__device__ __forceinline__ void mma16816(float* d, uint32_t a0, uint32_t a1, uint32_t a2,
                                         uint32_t a3, uint32_t b0, uint32_t b1) {
    asm("mma.sync.aligned.m16n8k16.row.col.f32.bf16.bf16.f32 "
        "{%0,%1,%2,%3}, {%4,%5,%6,%7}, {%8,%9}, {%0,%1,%2,%3};"
        : "+f"(d[0]), "+f"(d[1]), "+f"(d[2]), "+f"(d[3])
        : "r"(a0), "r"(a1), "r"(a2), "r"(a3), "r"(b0), "r"(b1));
}

// ============ K0: init + weight-fragment prep (fused; one fewer launch) ============
__global__ void k_initprep(const float* __restrict__ x, const float* __restrict__ tw,
                           const float* __restrict__ kan_base,
                           const float* __restrict__ kan_spline) {
    if (blockIdx.x < 1040) {
        int idx = blockIdx.x * blockDim.x + threadIdx.x;
        if (idx < 64 * 4160) {
            int b = idx / 4160, r = idx - b * 4160;
            if (r < 64) {
                float wl = tw[1023] * x[((size_t)b * 1024 + 1023) * 64 + r];
                float w0 = tw[0]    * x[(size_t)b * 1024 * 64 + r];
                d_sig[idx] = wl - w0;
            } else d_sig[idx] = 0.f;
        }
        if (idx < 64 * 128) { d_h1[idx] = 0.f; d_skip[idx] = 0.f; d_h2g[idx] = 0.f; }
    } else {
        int idx = (blockIdx.x - 1040) * blockDim.x + threadIdx.x;
        if (idx >= 36 * 16 * 32) return;
        int l = idx & 31, f = (idx >> 5) & 15, s = idx >> 9;
        int n = f * 8 + (l >> 2);
        int k0 = s * 16 + (l & 3) * 2;
        float w[4];
#pragma unroll
        for (int q = 0; q < 4; q++) {
            int k = k0 + (q >> 1) * 8 + (q & 1);
            w[q] = (k < 64) ? kan_base[k * 128 + n] : kan_spline[(size_t)(k - 64) * 128 + n];
        }
        uint4 v;
        split2(w[0], w[1], v.x, v.z);
        split2(w[2], w[3], v.y, v.w);
        d_Bfrag[idx] = v;
    }
}

// ============ K1: level-2 signature (unchanged) ============
#define KSIG_SMEM (2 * 128 * 64 * 4)
__global__ __launch_bounds__(256) void k_sig(const float* __restrict__ x,
                                             const float* __restrict__ tw) {
    extern __shared__ float sm[];
    float* sM = sm; float* sU = sm + 128 * 64;
    const int b = blockIdx.x, chunk = blockIdx.y, t0 = chunk * 128;
    const int steps = (chunk == 7) ? 127 : 128;
    const int tid = threadIdx.x;
    const size_t xb = (size_t)b * 1024 * 64;
    for (int e = tid; e < steps * 64; e += 256) {
        int t = e >> 6, d = e & 63;
        float wt0 = tw[t0 + t]     * x[xb + (size_t)(t0 + t) * 64 + d];
        float wt1 = tw[t0 + t + 1] * x[xb + (size_t)(t0 + t + 1) * 64 + d];
        float w0v = tw[0] * x[xb + d];
        sU[t * 64 + d] = wt1 - wt0;
        sM[t * 64 + d] = 0.5f * (wt0 + wt1) - w0v;
    }
    __syncthreads();
    const int jp = tid & 31, i0 = (tid >> 5) * 8;
    unsigned long long acc[8];
#pragma unroll
    for (int q = 0; q < 8; q++) acc[q] = 0ull;
#pragma unroll 2
    for (int t = 0; t < steps; t++) {
        const float4 m0 = *reinterpret_cast<const float4*>(&sM[t * 64 + i0]);
        const float4 m1 = *reinterpret_cast<const float4*>(&sM[t * 64 + i0 + 4]);
        const unsigned long long u2 =
            *reinterpret_cast<const unsigned long long*>(&sU[t * 64 + 2 * jp]);
        ffma2(acc[0], u2, bcast2(m0.x)); ffma2(acc[1], u2, bcast2(m0.y));
        ffma2(acc[2], u2, bcast2(m0.z)); ffma2(acc[3], u2, bcast2(m0.w));
        ffma2(acc[4], u2, bcast2(m1.x)); ffma2(acc[5], u2, bcast2(m1.y));
        ffma2(acc[6], u2, bcast2(m1.z)); ffma2(acc[7], u2, bcast2(m1.w));
    }
#pragma unroll
    for (int q = 0; q < 8; q++) {
        float2 f = unpack2(acc[q]);
        int i = i0 + q;
        atomicAdd(&d_sig[b * 4160 + 64 + i * 64 + 2 * jp],     f.x);
        atomicAdd(&d_sig[b * 4160 + 64 + i * 64 + 2 * jp + 1], f.y);
    }
}

// ============ K2: GRKAN layer 1 + skip via mma.sync — N-split x2 for occupancy ====
// 1066 CTAs: cid = (c2, nsel). c2: [0,52) base (5 ks), [52,468) spline (5 ks),
// [468,533) skip (4 ks). Each CTA covers 64 cols (nsel half). acc[4][4] -> low regs.
#define L1_SMEM (64 * 88 * 4)
__global__ __launch_bounds__(256) void k_lin1(const float* __restrict__ g1_base,
                                              const float* __restrict__ g1_spline,
                                              const float* __restrict__ skip_w) {
    extern __shared__ float feat[];            // [64][88] (pad 8)
    const int cid = blockIdx.x;
    const int nsel = cid & 1, c2 = cid >> 1;
    const float* Bw;
    float* outp;
    int ks0, nks, mode;
    if (c2 < 52)       { mode = 0; Bw = g1_base;   outp = d_h1;   ks0 = c2 * 5;         nks = 5; }
    else if (c2 < 468) { mode = 1; Bw = g1_spline; outp = d_h1;   ks0 = (c2 - 52) * 5;  nks = 5; }
    else               { mode = 2; Bw = skip_w;    outp = d_skip; ks0 = (c2 - 468) * 4; nks = 4; }
    const int tid = threadIdx.x;
    const int kk0 = ks0 * 16;
    // ---- stage A features: feat[b][i] for i in [0, nks*16) ----
    if (mode == 0) {
        for (int e = tid; e < 64 * 80; e += 256) {
            int b = e / 80, i = e - b * 80;
            feat[b * 88 + i] = siluf(d_sig[b * 4160 + kk0 + i]);
        }
    } else if (mode == 2) {
        for (int e = tid; e < 64 * 64; e += 256) {
            int b = e >> 6, i = e & 63;
            feat[b * 88 + i] = d_sig[b * 4160 + kk0 + i];
        }
    } else {
        const int d0 = kk0 >> 3;               // kk0 divisible by 8
        for (int e = tid; e < 64 * 10; e += 256) {
            int b = e / 10, dd = e - b * 10;
            float bas[8];
            bspline8(d_sig[b * 4160 + d0 + dd], bas);
#pragma unroll
            for (int nb = 0; nb < 8; nb++) feat[b * 88 + dd * 8 + nb] = bas[nb];
        }
    }
    __syncthreads();
    const int w = tid >> 5, lane = tid & 31;
    const int mt = w & 3, nq = w >> 2;
    const int wr = lane >> 2, kq = (lane & 3) * 2;
    const int m0 = mt * 16 + wr;               // rows m0, m0+8
    const int nbase = nsel * 64 + nq * 32;
    float acc[4][4];
#pragma unroll
    for (int f = 0; f < 4; f++)
#pragma unroll
        for (int q = 0; q < 4; q++) acc[f][q] = 0.f;

    for (int ks = 0; ks < nks; ks++) {
        const int kb = ks * 16 + kq;
        float2 f0 = *(const float2*)(&feat[m0 * 88 + kb]);
        float2 f1 = *(const float2*)(&feat[(m0 + 8) * 88 + kb]);
        float2 f2 = *(const float2*)(&feat[m0 * 88 + kb + 8]);
        float2 f3 = *(const float2*)(&feat[(m0 + 8) * 88 + kb + 8]);
        uint32_t ah[4], al[4];
        split2(f0.x, f0.y, ah[0], al[0]);
        split2(f1.x, f1.y, ah[1], al[1]);
        split2(f2.x, f2.y, ah[2], al[2]);
        split2(f3.x, f3.y, ah[3], al[3]);
        const float* Bp = Bw + (size_t)(kk0 + ks * 16 + kq) * 128;
#pragma unroll
        for (int f = 0; f < 4; f++) {
            const float* bp = Bp + nbase + f * 8 + wr;
            float w0 = bp[0];          // row kq
            float w1 = bp[128];        // row kq+1
            float w2 = bp[8 * 128];    // row kq+8
            float w3 = bp[9 * 128];    // row kq+9
            uint32_t bh0, bl0, bh1, bl1;
            split2(w0, w1, bh0, bl0);
            split2(w2, w3, bh1, bl1);
            mma16816(acc[f], ah[0], ah[1], ah[2], ah[3], bh0, bh1);  // hh
            mma16816(acc[f], ah[0], ah[1], ah[2], ah[3], bl0, bl1);  // hl
            mma16816(acc[f], al[0], al[1], al[2], al[3], bh0, bh1);  // lh
        }
    }
#pragma unroll
    for (int f = 0; f < 4; f++) {
        int c = nbase + f * 8 + (lane & 3) * 2;
        atomicAdd(&outp[m0 * 128 + c],           acc[f][0]);
        atomicAdd(&outp[m0 * 128 + c + 1],       acc[f][1]);
        atomicAdd(&outp[(m0 + 8) * 128 + c],     acc[f][2]);
        atomicAdd(&outp[(m0 + 8) * 128 + c + 1], acc[f][3]);
    }
}

// ============ K3a: h2 = kan_linear(h1, g2), split-K x4, 256 blocks ============
__global__ __launch_bounds__(128) void k_grkan2a(const float* __restrict__ g2_base,
                                                 const float* __restrict__ g2_spline) {
    __shared__ float s_sil[32];
    __shared__ float s_bas[32][8];
    const int b = blockIdx.x >> 2, kq = blockIdx.x & 3;
    const int u = threadIdx.x;
    const int k0 = kq * 32;
    if (u < 32) {
        float v = d_h1[b * 128 + k0 + u];
        s_sil[u] = siluf(v);
        bspline8(v, &s_bas[u][0]);
    }
    __syncthreads();
    float acc = 0.f;
#pragma unroll 8
    for (int kk = 0; kk < 32; kk++) {
        int k = k0 + kk;
        float h = s_sil[kk] * g2_base[k * 128 + u];
#pragma unroll
        for (int nb = 0; nb < 8; nb++)
            h += s_bas[kk][nb] * g2_spline[((size_t)k * 8 + nb) * 128 + u];
        acc += h;
    }
    atomicAdd(&d_h2g[b * 128 + u], acc);
}

// ============ K3b: gate + layernorm + softmax -> d_wts (64 blocks x 128) ============
__device__ __forceinline__ float bsum128(float v, volatile float* red) {
#pragma unroll
    for (int o = 16; o > 0; o >>= 1) v += __shfl_xor_sync(0xffffffffu, v, o);
    int w = threadIdx.x >> 5;
    __syncthreads();
    if ((threadIdx.x & 31) == 0) red[w] = v;
    __syncthreads();
    return red[0] + red[1] + red[2] + red[3];
}
__device__ __forceinline__ float bmax128(float v, volatile float* red) {
#pragma unroll
    for (int o = 16; o > 0; o >>= 1) v = fmaxf(v, __shfl_xor_sync(0xffffffffu, v, o));
    int w = threadIdx.x >> 5;
    __syncthreads();
    if ((threadIdx.x & 31) == 0) red[w] = v;
    __syncthreads();
    return fmaxf(fmaxf(red[0], red[1]), fmaxf(red[2], red[3]));
}
__global__ __launch_bounds__(128) void k_grkan2b(
    const float* __restrict__ skip_b,
    const float* __restrict__ gate_ws, const float* __restrict__ gate_bs,
    const float* __restrict__ gate_wv, const float* __restrict__ gate_bv,
    const float* __restrict__ ln_g, const float* __restrict__ ln_b) {
    __shared__ float s_h2[128];
    __shared__ float red[4];
    const int b = blockIdx.x;
    const int u = threadIdx.x;
    s_h2[u] = d_h2g[b * 128 + u];
    __syncthreads();
    float sa = 0.f, va = 0.f;
#pragma unroll 8
    for (int k = 0; k < 128; k++) {
        float h = s_h2[k];
        sa += h * gate_ws[k * 128 + u];
        va += h * gate_wv[k * 128 + u];
    }
    float gate = sigmf(sa + gate_bs[u]) * (va + gate_bv[u]);
    float y = d_skip[b * 128 + u] + skip_b[u] + gate;
    float mu = bsum128(y, red) * (1.f / 128.f);
    float dv = y - mu;
    float var = bsum128(dv * dv, red) * (1.f / 128.f);
    float z = ln_g[u] * dv / sqrtf(var + 1e-3f) + ln_b[u];
    float mx = bmax128(z, red);
    float ez = __expf(z - mx);
    float es = bsum128(ez, red);
    d_wts[b * 128 + u] = ez / es;
}

// ============ K4: final KAN via mma.sync bf16 split precision ============
// 256 CTAs x 2 tiles; __launch_bounds__(256,2) guarantees 2 CTAs/SM so one CTA's
// feature build overlaps the other's tensor work.
#define KM_SMEM    (8192 * 4 + 64 * 129 * 4 + 512)
__global__ __launch_bounds__(256, 2) void k_main(const float* __restrict__ x,
                                                 const float* __restrict__ tw,
                                                 float* __restrict__ out) {
    extern __shared__ float smf[];
    uint32_t* Ah = (uint32_t*)smf;                    // [4 sl][8 rt][32 lane][4 regs]
    uint32_t* Al = Ah + 4096;
    float* xt    = smf + 8192;                        // x^T tile [64][129]
    float* wts_s = xt + 64 * 129;
    const int tid = threadIdx.x, w = tid >> 5, lane = tid & 31;

    for (int tt = 0; tt < 2; tt++) {
        const int tile = blockIdx.x + tt * 256;
        const size_t row0 = (size_t)tile * 128;

        for (int e = tid; e < 2048; e += 256) {
            float4 v = ((const float4*)(x + row0 * 64))[e];
            int r = e >> 4, dd = (e & 15) * 4;
            xt[(dd + 0) * 129 + r] = v.x;
            xt[(dd + 1) * 129 + r] = v.y;
            xt[(dd + 2) * 129 + r] = v.z;
            xt[(dd + 3) * 129 + r] = v.w;
        }
        if (tid < 128) wts_s[tid] = d_wts[(tile >> 3) * 128 + tid];

        float acc[16][4];
#pragma unroll
        for (int f = 0; f < 16; f++)
#pragma unroll
            for (int q = 0; q < 4; q++) acc[f][q] = 0.f;

        for (int c = 0; c < 9; c++) {
            __syncthreads();        // staging/A-buffer visible & free
#pragma unroll
            for (int j = 0; j < 4; j++) {
                int it = tid + j * 256;          // 1024 items: [dl 8][r 128]
                int r = it & 127, dl = it >> 7;
                int rt = r >> 4, wr = r & 15, gid = wr & 7;
                int reg = ((wr < 8) ? 0 : 1) + (dl & 1) * 2;
                int slot = (((dl >> 1) * 8 + rt) * 32 + gid * 4) * 4 + reg;
                float t = tw[(row0 + r) & 1023];
                float vals[8];
                if (c == 0) {
#pragma unroll
                    for (int nb = 0; nb < 8; nb++)
                        vals[nb] = siluf(t * xt[(dl * 8 + nb) * 129 + r]);
                } else {
                    float wv = t * xt[(8 * (c - 1) + dl) * 129 + r];
                    bspline8(wv, vals);
                }
#pragma unroll
                for (int pj = 0; pj < 4; pj++) {
                    uint32_t h, l;
                    split2(vals[2 * pj], vals[2 * pj + 1], h, l);
                    Ah[slot + pj * 4] = h;
                    Al[slot + pj * 4] = l;
                }
            }
            __syncthreads();
#pragma unroll
            for (int sl = 0; sl < 4; sl++) {
                const uint4 a_h = ((const uint4*)Ah)[(sl * 8 + w) * 32 + lane];
                const uint4 a_l = ((const uint4*)Al)[(sl * 8 + w) * 32 + lane];
                const uint4* Bp = d_Bfrag + ((c * 4 + sl) * 16) * 32 + lane;
#pragma unroll
                for (int f = 0; f < 16; f++) {
                    const uint4 b = Bp[f * 32];
                    mma16816(acc[f], a_h.x, a_h.y, a_h.z, a_h.w, b.x, b.y);  // hh
                    mma16816(acc[f], a_h.x, a_h.y, a_h.z, a_h.w, b.z, b.w);  // hl
                    mma16816(acc[f], a_l.x, a_l.y, a_l.z, a_l.w, b.x, b.y);  // lh
                }
            }
        }
        __syncthreads();

        const int rlo = w * 16 + (lane >> 2);
#pragma unroll
        for (int f = 0; f < 16; f++) {
            int c0 = f * 8 + (lane & 3) * 2;
            float w0 = wts_s[c0], w1 = wts_s[c0 + 1];
            float2 v0 = make_float2(acc[f][0] * w0, acc[f][1] * w1);
            float2 v1 = make_float2(acc[f][2] * w0, acc[f][3] * w1);
            *(float2*)(out + (row0 + rlo) * 128 + c0)     = v0;
            *(float2*)(out + (row0 + rlo + 8) * 128 + c0) = v1;
        }
        __syncthreads();        // epilogue done before next tile overwrites buffers
    }
}

extern "C" void kernel_launch(void* const* d_in, const int* in_sizes, int n_in,
                              void* d_out, int out_size) {
    const float* x          = (const float*)d_in[0];
    const float* tw         = (const float*)d_in[1];
    const float* kan_base   = (const float*)d_in[2];
    const float* kan_spline = (const float*)d_in[3];
    const float* g1_base    = (const float*)d_in[4];
    const float* g1_spline  = (const float*)d_in[5];
    const float* g2_base    = (const float*)d_in[6];
    const float* g2_spline  = (const float*)d_in[7];
    const float* skip_w     = (const float*)d_in[8];
    const float* skip_b     = (const float*)d_in[9];
    const float* gate_ws    = (const float*)d_in[10];
    const float* gate_bs    = (const float*)d_in[11];
    const float* gate_wv    = (const float*)d_in[12];
    const float* gate_bv    = (const float*)d_in[13];
    const float* ln_g       = (const float*)d_in[14];
    const float* ln_b       = (const float*)d_in[15];
    float* out = (float*)d_out;

    cudaFuncSetAttribute(k_sig,  cudaFuncAttributeMaxDynamicSharedMemorySize, KSIG_SMEM);
    cudaFuncSetAttribute(k_main, cudaFuncAttributeMaxDynamicSharedMemorySize, KM_SMEM);

    k_initprep<<<1112, 256>>>(x, tw, kan_base, kan_spline);
    k_sig<<<dim3(64, 8), 256, KSIG_SMEM>>>(x, tw);
    k_lin1<<<1066, 256, L1_SMEM>>>(g1_base, g1_spline, skip_w);
    k_grkan2a<<<256, 128>>>(g2_base, g2_spline);
    k_grkan2b<<<64, 128>>>(skip_b, gate_ws, gate_bs, gate_wv, gate_bv, ln_g, ln_b);
    k_main<<<256, 256, KM_SMEM>>>(x, tw, out);
}

// round 17
// speedup vs baseline: 1.9834x; 1.1309x over previous
#include <cuda_runtime.h>
#include <cuda_bf16.h>
#include <cstdint>

// B=64, S=1024, D=64, U=128, NB=8, SIG_DIM=4160; final-KAN K = 64+512 = 576
// k_main: K = 36 ksteps of 16; N = 128 = 16 n-frags of 8.
// k_lin1: GRKAN layer-1 GEMMs, K order = [4160 silu | 33280 spline], plus skip.

__device__ float d_sig[64 * 4160];
__device__ float d_h1[64 * 128];
__device__ float d_h2g[64 * 128];
__device__ float d_skip[64 * 128];
__device__ float d_wts[64 * 128];
// B operand in m16n8k16 fragment layout: [kstep 36][nfrag 16][lane 32] = {bh0,bh1,bl0,bl1}
__device__ uint4 d_Bfrag[36 * 16 * 32];

__device__ __forceinline__ float siluf(float v) { return v / (1.f + __expf(-v)); }
__device__ __forceinline__ float sigmf(float v) { return 1.f / (1.f + __expf(-v)); }

// Cubic B-spline on uniform knots g(k)=0.4k-2.2: only 4 consecutive bases are
// nonzero. Closed-form uniform segment polynomials + selects.
__device__ __forceinline__ void bspline8(float x, float* o) {
    float xi = (x + 2.2f) * 2.5f;          // knot-space position
    float fi = floorf(xi);
    float t = xi - fi;
    int i = (int)fi;                        // interval; basis k nonzero iff i-3<=k<=i
    float t2 = t * t, t3 = t2 * t;
    float u = 1.f - t;
    float s0 = t3 * (1.f / 6.f);
    float s1 = (1.f / 6.f) + 0.5f * t + 0.5f * t2 - 0.5f * t3;
    float s2 = (4.f / 6.f) - t2 + 0.5f * t3;
    float s3 = u * u * u * (1.f / 6.f);
#pragma unroll
    for (int k = 0; k < 8; k++) {
        float v = (i == k) ? s0 : 0.f;
        v = (i == k + 1) ? s1 : v;
        v = (i == k + 2) ? s2 : v;
        v = (i == k + 3) ? s3 : v;
        o[k] = v;
    }
}

__device__ __forceinline__ void ffma2(unsigned long long& d, unsigned long long a,
                                      unsigned long long b) {
    asm("fma.rn.f32x2 %0, %1, %2, %0;" : "+l"(d) : "l"(a), "l"(b));
}
__device__ __forceinline__ unsigned long long bcast2(float v) {
    unsigned long long r; unsigned int u = __float_as_uint(v);
    asm("mov.b64 %0, {%1, %1};" : "=l"(r) : "r"(u));
    return r;
}
__device__ __forceinline__ float2 unpack2(unsigned long long v) {
    unsigned int lo, hi;
    asm("mov.b64 {%0, %1}, %2;" : "=r"(lo), "=r"(hi) : "l"(v));
    return make_float2(__uint_as_float(lo), __uint_as_float(hi));
}
// split fp32 pair -> packed bf16 hi pair + bf16 lo (residual) pair.
__device__ __forceinline__ void split2(float a, float b, uint32_t& h, uint32_t& l) {
    uint32_t hh;
    asm("cvt.rn.bf16x2.f32 %0, %1, %2;" : "=r"(hh) : "f"(b), "f"(a));  // lo=a, hi=b
    float ra = a - __uint_as_float(hh << 16);
    float rb = b - __uint_as_float(hh & 0xFFFF0000u);
    uint32_t ll;
    asm("cvt.rn.bf16x2.f32 %0, %1, %2;" : "=r"(ll) : "f"(rb), "f"(ra));
    h = hh; l = ll;
}
// m16n8k16 row.col bf16 MMA, fp32 accumulate in place
__device__ __forceinline__ void mma16816(float* d, uint32_t a0, uint32_t a1, uint32_t a2,
                                         uint32_t a3, uint32_t b0, uint32_t b1) {
    asm("mma.sync.aligned.m16n8k16.row.col.f32.bf16.bf16.f32 "
        "{%0,%1,%2,%3}, {%4,%5,%6,%7}, {%8,%9}, {%0,%1,%2,%3};"
        : "+f"(d[0]), "+f"(d[1]), "+f"(d[2]), "+f"(d[3])
        : "r"(a0), "r"(a1), "r"(a2), "r"(a3), "r"(b0), "r"(b1));
}

// ============ K0: init + weight-fragment prep (fused) ============
__global__ void k_initprep(const float* __restrict__ x, const float* __restrict__ tw,
                           const float* __restrict__ kan_base,
                           const float* __restrict__ kan_spline) {
    if (blockIdx.x < 1040) {
        int idx = blockIdx.x * blockDim.x + threadIdx.x;
        if (idx < 64 * 4160) {
            int b = idx / 4160, r = idx - b * 4160;
            if (r < 64) {
                float wl = tw[1023] * x[((size_t)b * 1024 + 1023) * 64 + r];
                float w0 = tw[0]    * x[(size_t)b * 1024 * 64 + r];
                d_sig[idx] = wl - w0;
            } else d_sig[idx] = 0.f;
        }
        if (idx < 64 * 128) { d_h1[idx] = 0.f; d_skip[idx] = 0.f; d_h2g[idx] = 0.f; }
    } else {
        int idx = (blockIdx.x - 1040) * blockDim.x + threadIdx.x;
        if (idx >= 36 * 16 * 32) return;
        int l = idx & 31, f = (idx >> 5) & 15, s = idx >> 9;
        int n = f * 8 + (l >> 2);
        int k0 = s * 16 + (l & 3) * 2;
        float w[4];
#pragma unroll
        for (int q = 0; q < 4; q++) {
            int k = k0 + (q >> 1) * 8 + (q & 1);
            w[q] = (k < 64) ? kan_base[k * 128 + n] : kan_spline[(size_t)(k - 64) * 128 + n];
        }
        uint4 v;
        split2(w[0], w[1], v.x, v.z);
        split2(w[2], w[3], v.y, v.w);
        d_Bfrag[idx] = v;
    }
}

// ============ K1: level-2 signature (unchanged) ============
#define KSIG_SMEM (2 * 128 * 64 * 4)
__global__ __launch_bounds__(256) void k_sig(const float* __restrict__ x,
                                             const float* __restrict__ tw) {
    extern __shared__ float sm[];
    float* sM = sm; float* sU = sm + 128 * 64;
    const int b = blockIdx.x, chunk = blockIdx.y, t0 = chunk * 128;
    const int steps = (chunk == 7) ? 127 : 128;
    const int tid = threadIdx.x;
    const size_t xb = (size_t)b * 1024 * 64;
    for (int e = tid; e < steps * 64; e += 256) {
        int t = e >> 6, d = e & 63;
        float wt0 = tw[t0 + t]     * x[xb + (size_t)(t0 + t) * 64 + d];
        float wt1 = tw[t0 + t + 1] * x[xb + (size_t)(t0 + t + 1) * 64 + d];
        float w0v = tw[0] * x[xb + d];
        sU[t * 64 + d] = wt1 - wt0;
        sM[t * 64 + d] = 0.5f * (wt0 + wt1) - w0v;
    }
    __syncthreads();
    const int jp = tid & 31, i0 = (tid >> 5) * 8;
    unsigned long long acc[8];
#pragma unroll
    for (int q = 0; q < 8; q++) acc[q] = 0ull;
#pragma unroll 2
    for (int t = 0; t < steps; t++) {
        const float4 m0 = *reinterpret_cast<const float4*>(&sM[t * 64 + i0]);
        const float4 m1 = *reinterpret_cast<const float4*>(&sM[t * 64 + i0 + 4]);
        const unsigned long long u2 =
            *reinterpret_cast<const unsigned long long*>(&sU[t * 64 + 2 * jp]);
        ffma2(acc[0], u2, bcast2(m0.x)); ffma2(acc[1], u2, bcast2(m0.y));
        ffma2(acc[2], u2, bcast2(m0.z)); ffma2(acc[3], u2, bcast2(m0.w));
        ffma2(acc[4], u2, bcast2(m1.x)); ffma2(acc[5], u2, bcast2(m1.y));
        ffma2(acc[6], u2, bcast2(m1.z)); ffma2(acc[7], u2, bcast2(m1.w));
    }
#pragma unroll
    for (int q = 0; q < 8; q++) {
        float2 f = unpack2(acc[q]);
        int i = i0 + q;
        atomicAdd(&d_sig[b * 4160 + 64 + i * 64 + 2 * jp],     f.x);
        atomicAdd(&d_sig[b * 4160 + 64 + i * 64 + 2 * jp + 1], f.y);
    }
}

// ============ K2: GRKAN layer 1 + skip via mma.sync (unchanged from R15) ============
#define L1_SMEM (64 * 88 * 4)
__global__ __launch_bounds__(256) void k_lin1(const float* __restrict__ g1_base,
                                              const float* __restrict__ g1_spline,
                                              const float* __restrict__ skip_w) {
    extern __shared__ float feat[];            // [64][88] (pad 8)
    const int cid = blockIdx.x;
    const int nsel = cid & 1, c2 = cid >> 1;
    const float* Bw;
    float* outp;
    int ks0, nks, mode;
    if (c2 < 52)       { mode = 0; Bw = g1_base;   outp = d_h1;   ks0 = c2 * 5;         nks = 5; }
    else if (c2 < 468) { mode = 1; Bw = g1_spline; outp = d_h1;   ks0 = (c2 - 52) * 5;  nks = 5; }
    else               { mode = 2; Bw = skip_w;    outp = d_skip; ks0 = (c2 - 468) * 4; nks = 4; }
    const int tid = threadIdx.x;
    const int kk0 = ks0 * 16;
    if (mode == 0) {
        for (int e = tid; e < 64 * 80; e += 256) {
            int b = e / 80, i = e - b * 80;
            feat[b * 88 + i] = siluf(d_sig[b * 4160 + kk0 + i]);
        }
    } else if (mode == 2) {
        for (int e = tid; e < 64 * 64; e += 256) {
            int b = e >> 6, i = e & 63;
            feat[b * 88 + i] = d_sig[b * 4160 + kk0 + i];
        }
    } else {
        const int d0 = kk0 >> 3;
        for (int e = tid; e < 64 * 10; e += 256) {
            int b = e / 10, dd = e - b * 10;
            float bas[8];
            bspline8(d_sig[b * 4160 + d0 + dd], bas);
#pragma unroll
            for (int nb = 0; nb < 8; nb++) feat[b * 88 + dd * 8 + nb] = bas[nb];
        }
    }
    __syncthreads();
    const int w = tid >> 5, lane = tid & 31;
    const int mt = w & 3, nq = w >> 2;
    const int wr = lane >> 2, kq = (lane & 3) * 2;
    const int m0 = mt * 16 + wr;
    const int nbase = nsel * 64 + nq * 32;
    float acc[4][4];
#pragma unroll
    for (int f = 0; f < 4; f++)
#pragma unroll
        for (int q = 0; q < 4; q++) acc[f][q] = 0.f;

    for (int ks = 0; ks < nks; ks++) {
        const int kb = ks * 16 + kq;
        float2 f0 = *(const float2*)(&feat[m0 * 88 + kb]);
        float2 f1 = *(const float2*)(&feat[(m0 + 8) * 88 + kb]);
        float2 f2 = *(const float2*)(&feat[m0 * 88 + kb + 8]);
        float2 f3 = *(const float2*)(&feat[(m0 + 8) * 88 + kb + 8]);
        uint32_t ah[4], al[4];
        split2(f0.x, f0.y, ah[0], al[0]);
        split2(f1.x, f1.y, ah[1], al[1]);
        split2(f2.x, f2.y, ah[2], al[2]);
        split2(f3.x, f3.y, ah[3], al[3]);
        const float* Bp = Bw + (size_t)(kk0 + ks * 16 + kq) * 128;
#pragma unroll
        for (int f = 0; f < 4; f++) {
            const float* bp = Bp + nbase + f * 8 + wr;
            float w0 = bp[0];
            float w1 = bp[128];
            float w2 = bp[8 * 128];
            float w3 = bp[9 * 128];
            uint32_t bh0, bl0, bh1, bl1;
            split2(w0, w1, bh0, bl0);
            split2(w2, w3, bh1, bl1);
            mma16816(acc[f], ah[0], ah[1], ah[2], ah[3], bh0, bh1);  // hh
            mma16816(acc[f], ah[0], ah[1], ah[2], ah[3], bl0, bl1);  // hl
            mma16816(acc[f], al[0], al[1], al[2], al[3], bh0, bh1);  // lh
        }
    }
#pragma unroll
    for (int f = 0; f < 4; f++) {
        int c = nbase + f * 8 + (lane & 3) * 2;
        atomicAdd(&outp[m0 * 128 + c],           acc[f][0]);
        atomicAdd(&outp[m0 * 128 + c + 1],       acc[f][1]);
        atomicAdd(&outp[(m0 + 8) * 128 + c],     acc[f][2]);
        atomicAdd(&outp[(m0 + 8) * 128 + c + 1], acc[f][3]);
    }
}

// ============ K3a: h2 = kan_linear(h1, g2), split-K x16, 1024 blocks ============
// Per block: 8 k-values of one batch. Per-thread chain: 8 iters x 9 coalesced loads.
__global__ __launch_bounds__(128) void k_grkan2a(const float* __restrict__ g2_base,
                                                 const float* __restrict__ g2_spline) {
    __shared__ float s_sil[8];
    __shared__ float s_bas[8][8];
    const int b = blockIdx.x >> 4, kc = blockIdx.x & 15;
    const int u = threadIdx.x;
    const int k0 = kc * 8;
    if (u < 8) {
        float v = d_h1[b * 128 + k0 + u];
        s_sil[u] = siluf(v);
        bspline8(v, &s_bas[u][0]);
    }
    __syncthreads();
    float acc = 0.f;
#pragma unroll
    for (int kk = 0; kk < 8; kk++) {
        int k = k0 + kk;
        float h = s_sil[kk] * g2_base[k * 128 + u];
#pragma unroll
        for (int nb = 0; nb < 8; nb++)
            h += s_bas[kk][nb] * g2_spline[((size_t)k * 8 + nb) * 128 + u];
        acc += h;
    }
    atomicAdd(&d_h2g[b * 128 + u], acc);
}

// ============ K3b: gate + layernorm + softmax -> d_wts (64 blocks x 256, k-split x2) ==
__device__ __forceinline__ float bsum256(float v, volatile float* red) {
#pragma unroll
    for (int o = 16; o > 0; o >>= 1) v += __shfl_xor_sync(0xffffffffu, v, o);
    int w = threadIdx.x >> 5;
    __syncthreads();
    if ((threadIdx.x & 31) == 0) red[w] = v;
    __syncthreads();
    float s = 0.f;
#pragma unroll
    for (int i = 0; i < 8; i++) s += red[i];
    return s;
}
__device__ __forceinline__ float bmax256(float v, volatile float* red) {
#pragma unroll
    for (int o = 16; o > 0; o >>= 1) v = fmaxf(v, __shfl_xor_sync(0xffffffffu, v, o));
    int w = threadIdx.x >> 5;
    __syncthreads();
    if ((threadIdx.x & 31) == 0) red[w] = v;
    __syncthreads();
    float s = red[0];
#pragma unroll
    for (int i = 1; i < 8; i++) s = fmaxf(s, red[i]);
    return s;
}
__global__ __launch_bounds__(256) void k_grkan2b(
    const float* __restrict__ skip_b,
    const float* __restrict__ gate_ws, const float* __restrict__ gate_bs,
    const float* __restrict__ gate_wv, const float* __restrict__ gate_bv,
    const float* __restrict__ ln_g, const float* __restrict__ ln_b) {
    __shared__ float s_h2[128];
    __shared__ float s_pa[128], s_pv[128];
    __shared__ float red[8];
    const int b = blockIdx.x;
    const int tid = threadIdx.x;
    const int u = tid & 127;
    const int kh = tid >> 7;           // 0/1 k-half
    if (tid < 128) s_h2[tid] = d_h2g[b * 128 + tid];
    __syncthreads();
    float sa = 0.f, va = 0.f;
    const int kb = kh * 64;
#pragma unroll 8
    for (int kk = 0; kk < 64; kk++) {
        int k = kb + kk;
        float h = s_h2[k];
        sa += h * gate_ws[k * 128 + u];
        va += h * gate_wv[k * 128 + u];
    }
    if (kh == 1) { s_pa[u] = sa; s_pv[u] = va; }
    __syncthreads();
    float y = 0.f;
    if (kh == 0) {
        sa += s_pa[u]; va += s_pv[u];
        float gate = sigmf(sa + gate_bs[u]) * (va + gate_bv[u]);
        y = d_skip[b * 128 + u] + skip_b[u] + gate;
    }
    float v = (kh == 0) ? y : 0.f;
    float mu = bsum256(v, red) * (1.f / 128.f);
    float dv = (kh == 0) ? (v - mu) : 0.f;
    float var = bsum256(dv * dv, red) * (1.f / 128.f);
    float z = (kh == 0) ? (ln_g[u] * dv / sqrtf(var + 1e-3f) + ln_b[u]) : -1e30f;
    float mx = bmax256(z, red);
    float ez = (kh == 0) ? __expf(z - mx) : 0.f;
    float es = bsum256(ez, red);
    if (kh == 0) d_wts[b * 128 + u] = ez / es;
}

// ============ K4: final KAN via mma.sync bf16 split precision (unchanged) ============
#define KM_SMEM    (8192 * 4 + 64 * 129 * 4 + 512)
__global__ __launch_bounds__(256, 2) void k_main(const float* __restrict__ x,
                                                 const float* __restrict__ tw,
                                                 float* __restrict__ out) {
    extern __shared__ float smf[];
    uint32_t* Ah = (uint32_t*)smf;                    // [4 sl][8 rt][32 lane][4 regs]
    uint32_t* Al = Ah + 4096;
    float* xt    = smf + 8192;                        // x^T tile [64][129]
    float* wts_s = xt + 64 * 129;
    const int tid = threadIdx.x, w = tid >> 5, lane = tid & 31;

    for (int tt = 0; tt < 2; tt++) {
        const int tile = blockIdx.x + tt * 256;
        const size_t row0 = (size_t)tile * 128;

        for (int e = tid; e < 2048; e += 256) {
            float4 v = ((const float4*)(x + row0 * 64))[e];
            int r = e >> 4, dd = (e & 15) * 4;
            xt[(dd + 0) * 129 + r] = v.x;
            xt[(dd + 1) * 129 + r] = v.y;
            xt[(dd + 2) * 129 + r] = v.z;
            xt[(dd + 3) * 129 + r] = v.w;
        }
        if (tid < 128) wts_s[tid] = d_wts[(tile >> 3) * 128 + tid];

        float acc[16][4];
#pragma unroll
        for (int f = 0; f < 16; f++)
#pragma unroll
            for (int q = 0; q < 4; q++) acc[f][q] = 0.f;

        for (int c = 0; c < 9; c++) {
            __syncthreads();
#pragma unroll
            for (int j = 0; j < 4; j++) {
                int it = tid + j * 256;          // 1024 items: [dl 8][r 128]
                int r = it & 127, dl = it >> 7;
                int rt = r >> 4, wr = r & 15, gid = wr & 7;
                int reg = ((wr < 8) ? 0 : 1) + (dl & 1) * 2;
                int slot = (((dl >> 1) * 8 + rt) * 32 + gid * 4) * 4 + reg;
                float t = tw[(row0 + r) & 1023];
                float vals[8];
                if (c == 0) {
#pragma unroll
                    for (int nb = 0; nb < 8; nb++)
                        vals[nb] = siluf(t * xt[(dl * 8 + nb) * 129 + r]);
                } else {
                    float wv = t * xt[(8 * (c - 1) + dl) * 129 + r];
                    bspline8(wv, vals);
                }
#pragma unroll
                for (int pj = 0; pj < 4; pj++) {
                    uint32_t h, l;
                    split2(vals[2 * pj], vals[2 * pj + 1], h, l);
                    Ah[slot + pj * 4] = h;
                    Al[slot + pj * 4] = l;
                }
            }
            __syncthreads();
#pragma unroll
            for (int sl = 0; sl < 4; sl++) {
                const uint4 a_h = ((const uint4*)Ah)[(sl * 8 + w) * 32 + lane];
                const uint4 a_l = ((const uint4*)Al)[(sl * 8 + w) * 32 + lane];
                const uint4* Bp = d_Bfrag + ((c * 4 + sl) * 16) * 32 + lane;
#pragma unroll
                for (int f = 0; f < 16; f++) {
                    const uint4 b = Bp[f * 32];
                    mma16816(acc[f], a_h.x, a_h.y, a_h.z, a_h.w, b.x, b.y);  // hh
                    mma16816(acc[f], a_h.x, a_h.y, a_h.z, a_h.w, b.z, b.w);  // hl
                    mma16816(acc[f], a_l.x, a_l.y, a_l.z, a_l.w, b.x, b.y);  // lh
                }
            }
        }
        __syncthreads();

        const int rlo = w * 16 + (lane >> 2);
#pragma unroll
        for (int f = 0; f < 16; f++) {
            int c0 = f * 8 + (lane & 3) * 2;
            float w0 = wts_s[c0], w1 = wts_s[c0 + 1];
            float2 v0 = make_float2(acc[f][0] * w0, acc[f][1] * w1);
            float2 v1 = make_float2(acc[f][2] * w0, acc[f][3] * w1);
            *(float2*)(out + (row0 + rlo) * 128 + c0)     = v0;
            *(float2*)(out + (row0 + rlo + 8) * 128 + c0) = v1;
        }
        __syncthreads();
    }
}

extern "C" void kernel_launch(void* const* d_in, const int* in_sizes, int n_in,
                              void* d_out, int out_size) {
    const float* x          = (const float*)d_in[0];
    const float* tw         = (const float*)d_in[1];
    const float* kan_base   = (const float*)d_in[2];
    const float* kan_spline = (const float*)d_in[3];
    const float* g1_base    = (const float*)d_in[4];
    const float* g1_spline  = (const float*)d_in[5];
    const float* g2_base    = (const float*)d_in[6];
    const float* g2_spline  = (const float*)d_in[7];
    const float* skip_w     = (const float*)d_in[8];
    const float* skip_b     = (const float*)d_in[9];
    const float* gate_ws    = (const float*)d_in[10];
    const float* gate_bs    = (const float*)d_in[11];
    const float* gate_wv    = (const float*)d_in[12];
    const float* gate_bv    = (const float*)d_in[13];
    const float* ln_g       = (const float*)d_in[14];
    const float* ln_b       = (const float*)d_in[15];
    float* out = (float*)d_out;

    cudaFuncSetAttribute(k_sig,  cudaFuncAttributeMaxDynamicSharedMemorySize, KSIG_SMEM);
    cudaFuncSetAttribute(k_main, cudaFuncAttributeMaxDynamicSharedMemorySize, KM_SMEM);

    k_initprep<<<1112, 256>>>(x, tw, kan_base, kan_spline);
    k_sig<<<dim3(64, 8), 256, KSIG_SMEM>>>(x, tw);
    k_lin1<<<1066, 256, L1_SMEM>>>(g1_base, g1_spline, skip_w);
    k_grkan2a<<<1024, 128>>>(g2_base, g2_spline);
    k_grkan2b<<<64, 256>>>(skip_b, gate_ws, gate_bs, gate_wv, gate_bv, ln_g, ln_b);
    k_main<<<256, 256, KM_SMEM>>>(x, tw, out);
}